// round 4
// baseline (speedup 1.0000x reference)
#include <cuda_runtime.h>
#include <cooperative_groups.h>

namespace cg = cooperative_groups;

// WaveRNN_77927886618842 — 2D acoustic FDTD, 500 steps, 8 shots, 256x256, 128 rec.
// One persistent cluster per shot: 8 CTAs x 1024 threads, all 500 steps in one
// kernel. cur/next pressure in SMEM ping-pong, p_prev + c2 in registers,
// z-halo via DSMEM, x-halo via shfl, per-step ordering via cluster.sync().

#define NT   500
#define NS   8
#define NZ   256
#define NX   256
#define NREC 128
#define CPS  8              // CTAs per shot == cluster size
#define ROWS 32             // NZ / CPS rows per CTA
#define TPB  1024
#define DT_OVER_DX 1.0e-4f  // 0.001 / 10.0

__global__ void __cluster_dims__(CPS, 1, 1) __launch_bounds__(TPB, 1)
wave_cluster_kernel(const float* __restrict__ x,    // (NT, NS)
                    const float* __restrict__ vp,   // (NZ, NX)
                    const int*   __restrict__ src,  // (NS, 2)
                    const int*   __restrict__ rec,  // (NS, NREC, 2)
                    float*       __restrict__ out)  // (NT, NS, NREC)
{
    extern __shared__ float smem[];
    float* bufA = smem;                 // ROWS*NX floats = 32 KB
    float* bufB = smem + ROWS * NX;     // 32 KB

    cg::cluster_group cluster = cg::this_cluster();
    const int rank = cluster.block_rank();        // 0..7 (z-slab index)
    const int shot = blockIdx.x / CPS;            // 0..7
    const int tid  = threadIdx.x;
    const int lane = tid & 31;
    const int x4   = tid & 63;                    // float4 column 0..63
    const int zg   = tid >> 6;                    // 0..15, two rows each (warp-uniform)
    const int zl0  = zg * 2;                      // local rows zl0, zl0+1
    const int gz0  = rank * ROWS + zl0;           // global z of row 0

    float4* Av = (float4*)bufA;
    float4* Bv = (float4*)bufB;
    const float4 zero4 = make_float4(0.f, 0.f, 0.f, 0.f);

    // ---- init: zero both buffers (each thread owns its 8 cells) ----
    Av[zl0 * 64 + x4]       = zero4;
    Av[(zl0 + 1) * 64 + x4] = zero4;
    Bv[zl0 * 64 + x4]       = zero4;
    Bv[(zl0 + 1) * 64 + x4] = zero4;

    // ---- c2 = (vp * DT/DX)^2 into registers ----
    float4 c2a, c2b;
    {
        const float4* vpv = (const float4*)vp;
        float4 v0 = vpv[gz0 * 64 + x4];
        float4 v1 = vpv[(gz0 + 1) * 64 + x4];
        c2a.x = v0.x * DT_OVER_DX; c2a.y = v0.y * DT_OVER_DX;
        c2a.z = v0.z * DT_OVER_DX; c2a.w = v0.w * DT_OVER_DX;
        c2b.x = v1.x * DT_OVER_DX; c2b.y = v1.y * DT_OVER_DX;
        c2b.z = v1.z * DT_OVER_DX; c2b.w = v1.w * DT_OVER_DX;
        c2a.x *= c2a.x; c2a.y *= c2a.y; c2a.z *= c2a.z; c2a.w *= c2a.w;
        c2b.x *= c2b.x; c2b.y *= c2b.y; c2b.z *= c2b.z; c2b.w *= c2b.w;
    }

    // ---- source cell ownership ----
    const int sz  = src[2 * shot];
    const int sx  = src[2 * shot + 1];
    const int sx4 = sx >> 2;
    const int sxl = sx & 3;
    const bool src0 = (sz == gz0)     && (sx4 == x4);
    const bool src1 = (sz == gz0 + 1) && (sx4 == x4);
    const float* __restrict__ xs = x + shot;      // x[t*NS + shot] = xs[t*NS]

    // ---- receiver assignment: thread tid<128 owns receiver tid of this shot ----
    int  rzl = 0, rxp = 0;
    bool mine = false;
    if (tid < NREC) {
        int rz = rec[(shot * NREC + tid) * 2];
        rxp    = rec[(shot * NREC + tid) * 2 + 1];
        mine   = ((rz >> 5) == rank);             // ROWS == 32
        rzl    = rz & 31;
    }
    float* __restrict__ outp = out + shot * NREC + tid;   // += NS*NREC per step

    // ---- DSMEM halo pointers (fixed for the whole run) ----
    float4* upA = (rank > 0)       ? (float4*)cluster.map_shared_rank((void*)bufA, rank - 1) : nullptr;
    float4* upB = (rank > 0)       ? (float4*)cluster.map_shared_rank((void*)bufB, rank - 1) : nullptr;
    float4* dnA = (rank < CPS - 1) ? (float4*)cluster.map_shared_rank((void*)bufA, rank + 1) : nullptr;
    float4* dnB = (rank < CPS - 1) ? (float4*)cluster.map_shared_rank((void*)bufB, rank + 1) : nullptr;

    float4 pva = zero4, pvb = zero4;   // p_prev for the two owned rows

    cluster.sync();   // zeros visible cluster-wide before step 0 halo reads

    for (int t = 0; t < NT; ++t) {
        float4* curv   = (t & 1) ? Bv  : Av;
        float4* nxtv   = (t & 1) ? Av  : Bv;
        float4* upRem  = (t & 1) ? upB : upA;
        float4* dnRem  = (t & 1) ? dnB : dnA;
        float*  curs   = (float*)curv;

        // rows zl0-1 .. zl0+2 (float4 each)
        float4 r0 = curv[zl0 * 64 + x4];
        float4 r1 = curv[(zl0 + 1) * 64 + x4];
        float4 rm1, r2;
        if (zg > 0)        rm1 = curv[(zl0 - 1) * 64 + x4];
        else               rm1 = upRem ? upRem[(ROWS - 1) * 64 + x4] : zero4;
        if (zg < 15)       r2  = curv[(zl0 + 2) * 64 + x4];
        else               r2  = dnRem ? dnRem[x4] : zero4;

        // x-neighbors via shfl; warp-edge lanes fall back to SMEM / zero pad
        float L0 = __shfl_up_sync(0xffffffffu, r0.w, 1);
        float R0 = __shfl_down_sync(0xffffffffu, r0.x, 1);
        float L1 = __shfl_up_sync(0xffffffffu, r1.w, 1);
        float R1 = __shfl_down_sync(0xffffffffu, r1.x, 1);
        if (lane == 0) {
            L0 = (x4 == 0) ? 0.f : curs[zl0 * NX + x4 * 4 - 1];
            L1 = (x4 == 0) ? 0.f : curs[(zl0 + 1) * NX + x4 * 4 - 1];
        }
        if (lane == 31) {
            R0 = (x4 == 63) ? 0.f : curs[zl0 * NX + x4 * 4 + 4];
            R1 = (x4 == 63) ? 0.f : curs[(zl0 + 1) * NX + x4 * 4 + 4];
        }

        // row zl0: up=rm1, dn=r1
        float4 lap0;
        lap0.x = rm1.x + r1.x + L0   + r0.y - 4.f * r0.x;
        lap0.y = rm1.y + r1.y + r0.x + r0.z - 4.f * r0.y;
        lap0.z = rm1.z + r1.z + r0.y + r0.w - 4.f * r0.z;
        lap0.w = rm1.w + r1.w + r0.z + R0   - 4.f * r0.w;
        float4 p0;
        p0.x = 2.f * r0.x - pva.x + c2a.x * lap0.x;
        p0.y = 2.f * r0.y - pva.y + c2a.y * lap0.y;
        p0.z = 2.f * r0.z - pva.z + c2a.z * lap0.z;
        p0.w = 2.f * r0.w - pva.w + c2a.w * lap0.w;
        pva = r0;

        // row zl0+1: up=r0, dn=r2
        float4 lap1;
        lap1.x = r0.x + r2.x + L1   + r1.y - 4.f * r1.x;
        lap1.y = r0.y + r2.y + r1.x + r1.z - 4.f * r1.y;
        lap1.z = r0.z + r2.z + r1.y + r1.w - 4.f * r1.z;
        lap1.w = r0.w + r2.w + r1.z + R1   - 4.f * r1.w;
        float4 p1;
        p1.x = 2.f * r1.x - pvb.x + c2b.x * lap1.x;
        p1.y = 2.f * r1.y - pvb.y + c2b.y * lap1.y;
        p1.z = 2.f * r1.z - pvb.z + c2b.z * lap1.z;
        p1.w = 2.f * r1.w - pvb.w + c2b.w * lap1.w;
        pvb = r1;

        // source injection
        if (src0 | src1) {
            int t_off = (t + 2 < NT - 1) ? (t + 2) : (NT - 1);
            float amp = xs[t_off * NS] + xs[t * NS];
            if (src0) {
                if      (sxl == 0) p0.x += amp;
                else if (sxl == 1) p0.y += amp;
                else if (sxl == 2) p0.z += amp;
                else               p0.w += amp;
            } else {
                if      (sxl == 0) p1.x += amp;
                else if (sxl == 1) p1.y += amp;
                else if (sxl == 2) p1.z += amp;
                else               p1.w += amp;
            }
        }

        nxtv[zl0 * 64 + x4]       = p0;
        nxtv[(zl0 + 1) * 64 + x4] = p1;

        cluster.sync();   // step t complete cluster-wide (writes + halo visibility)

        // receiver gather for step t (reads the just-written buffer, own SMEM)
        if (mine) {
            const float* ns = (const float*)nxtv;
            outp[t * (NS * NREC)] = ns[rzl * NX + rxp];
        }
    }
}

extern "C" void kernel_launch(void* const* d_in, const int* in_sizes, int n_in,
                              void* d_out, int out_size)
{
    const float* x   = (const float*)d_in[0];
    const float* vp  = (const float*)d_in[1];
    const int*   src = (const int*)d_in[2];
    const int*   rec = (const int*)d_in[3];
    float*       out = (float*)d_out;
    (void)in_sizes; (void)n_in; (void)out_size;

    const size_t smem_bytes = 2u * ROWS * NX * sizeof(float);   // 64 KB
    cudaFuncSetAttribute(wave_cluster_kernel,
                         cudaFuncAttributeMaxDynamicSharedMemorySize,
                         (int)smem_bytes);

    wave_cluster_kernel<<<NS * CPS, TPB, smem_bytes>>>(x, vp, src, rec, out);
}